// round 14
// baseline (speedup 1.0000x reference)
#include <cuda_runtime.h>
#include <math.h>

#define NPTS 8192
#define NPAIRS (NPTS / 2)       // 4096
#define NBATCH 4
#define KNN 30
#define TPB 512
#define PPB 256                 // points per block
#define HALFP 2048              // candidate PAIRS per thread (= 4096 candidates)
#define CHUNKS (NPTS / PPB)     // 32
#define GRID (NBATCH * CHUNKS)  // 128
#define FMAXV 3.4028235e38f
#define TIECAP 4

typedef unsigned long long u64;

// f32x2 packed ops (sm_103a FFMA2 path; PTX-only)
#define F2_FMA(o,a,b,c) asm("fma.rn.f32x2 %0,%1,%2,%3;" : "=l"(o) : "l"(a),"l"(b),"l"(c))
#define F2_MUL(o,a,b)   asm("mul.rn.f32x2 %0,%1,%2;"    : "=l"(o) : "l"(a),"l"(b))
#define F2_ADD(o,a,b)   asm("add.rn.f32x2 %0,%1,%2;"    : "=l"(o) : "l"(a),"l"(b))

__device__ __forceinline__ u64 pack2(float lo, float hi) {
    u64 r; asm("mov.b64 %0,{%1,%2};" : "=l"(r) : "f"(lo), "f"(hi)); return r;
}
__device__ __forceinline__ void unpack2(u64 v, float& lo, float& hi) {
    asm("mov.b64 {%0,%1},%2;" : "=f"(lo), "=f"(hi) : "l"(v));
}

// smem (bytes): float4 spair[NPTS] | float sbd[30*512] (reused as int strict)
//             | int ties[TIECAP*512] | float sthr[256] | int scnt[512] | int tcnt[512]
#define OFF_SP    0
#define OFF_SBD   (NPTS * 16)                    // 131072
#define OFF_TIES  (OFF_SBD + KNN * TPB * 4)      // 192512
#define OFF_STHR  (OFF_TIES + TIECAP * TPB * 4)  // 200704
#define OFF_SCNT  (OFF_STHR + PPB * 4)           // 201728
#define OFF_TCNT  (OFF_SCNT + TPB * 4)           // 203776
#define SMEM_BYTES (OFF_TCNT + TPB * 4)          // 205824

// Fetch candidate j's coords from the pair-packed layout.
__device__ __forceinline__ void fetch_pt(const float4* sp, int j,
                                         float& px, float& py, float& pz) {
    const float4 A = sp[(j >> 1) * 2];
    const float4 B = sp[(j >> 1) * 2 + 1];
    const bool hi = j & 1;
    px = hi ? A.y : A.x;
    py = hi ? A.w : A.z;
    pz = hi ? B.y : B.x;
}

__global__ __launch_bounds__(TPB) void knn_normals_kernel(
    const float* __restrict__ x, float* __restrict__ out)
{
    extern __shared__ char smem_raw[];
    float4* spair = (float4*)(smem_raw + OFF_SP);
    float*  sbd   = (float*)(smem_raw + OFF_SBD);
    int*    sidx  = (int*)(smem_raw + OFF_SBD);   // reuse after merge
    int*    sties = (int*)(smem_raw + OFF_TIES);
    float*  sthr  = (float*)(smem_raw + OFF_STHR);
    int*    scnt  = (int*)(smem_raw + OFF_SCNT);
    int*    tcnt  = (int*)(smem_raw + OFF_TCNT);

    const int tid  = threadIdx.x;
    const int pid  = tid & (PPB - 1);
    const int half = tid >> 8;                    // 0 or 1
    const int plo  = half * HALFP;                // starting pair index

    const int batch = blockIdx.x / CHUNKS;
    const int chunk = blockIdx.x % CHUNKS;
    const float* __restrict__ xb = x + (size_t)batch * 3 * NPTS;

    // Build pair-packed smem: spair[2p]   = (x0, x1, y0, y1)
    //                         spair[2p+1] = (z0, z1, xx0, xx1)
    // xx rounded exactly as the reference (squares, then left-to-right sum).
    for (int p = tid; p < NPAIRS; p += TPB) {
        int j0 = 2 * p, j1 = 2 * p + 1;
        float x0 = xb[j0],            x1 = xb[j1];
        float y0 = xb[NPTS + j0],     y1 = xb[NPTS + j1];
        float z0 = xb[2 * NPTS + j0], z1 = xb[2 * NPTS + j1];
        float w0 = __fadd_rn(__fadd_rn(__fmul_rn(x0, x0), __fmul_rn(y0, y0)),
                             __fmul_rn(z0, z0));
        float w1 = __fadd_rn(__fadd_rn(__fmul_rn(x1, x1), __fmul_rn(y1, y1)),
                             __fmul_rn(z1, z1));
        spair[2 * p]     = make_float4(x0, x1, y0, y1);
        spair[2 * p + 1] = make_float4(z0, z1, w0, w1);
    }
    __syncthreads();

    const int i = chunk * PPB + pid;
    float xi, yi, zi;
    fetch_pt(spair, i, xi, yi, zi);
    const float4 Bi = spair[(i >> 1) * 2 + 1];
    const float xxi = (i & 1) ? Bi.w : Bi.z;

    const u64 xi2 = pack2(xi, xi);
    const u64 yi2 = pack2(yi, yi);
    const u64 zi2 = pack2(zi, zi);
    const u64 xxi2 = pack2(xxi, xxi);
    const u64 n2 = pack2(-2.0f, -2.0f);

    const ulonglong2* __restrict__ sp2 = (const ulonglong2*)spair;

    // ---- Pass 1 over this thread's half: 30 smallest values, sorted
    // descending (bd[0]=max). Packed f32x2 distances, divergent insert.
    float bd[KNN];
    #pragma unroll
    for (int t = 0; t < KNN; t++) bd[t] = FMAXV;
    float thr = FMAXV;

    #pragma unroll 4
    for (int pp = 0; pp < HALFP; pp++) {
        const int p = plo + pp;
        ulonglong2 P0 = sp2[2 * p];      // (x0,x1 | y0,y1)
        ulonglong2 P1 = sp2[2 * p + 1];  // (z0,z1 | xx0,xx1)
        u64 sump, mp, t1, dotp, dp;
        F2_ADD(sump, xxi2, P1.y);                 // xxi + xx_j
        F2_MUL(mp, P0.x, xi2);                    // x*x'
        F2_FMA(t1, P0.y, yi2, mp);                // + y*y'
        F2_FMA(dotp, P1.x, zi2, t1);              // + z*z'  (= dot)
        F2_FMA(dp, dotp, n2, sump);               // (xxi+xxj) - 2*dot, 1 rounding
        float d0, d1;
        unpack2(dp, d0, d1);
        if (fminf(d0, d1) < thr) {
            // Inserting d >= bd[0] is a no-op of the identity, but the branch
            // keeps the common single-admit case cheap.
            if (d0 < thr) {
                #pragma unroll
                for (int t = 0; t < KNN; t++) {
                    float below = (t < KNN - 1) ? bd[t + 1] : -FMAXV;
                    bd[t] = fminf(bd[t], fmaxf(below, d0));
                }
                thr = bd[0];
            }
            if (d1 < thr) {
                #pragma unroll
                for (int t = 0; t < KNN; t++) {
                    float below = (t < KNN - 1) ? bd[t + 1] : -FMAXV;
                    bd[t] = fminf(bd[t], fmaxf(below, d1));
                }
                thr = bd[0];
            }
        }
    }

    // Publish per-half sorted values (stride TPB: conflict-free).
    #pragma unroll
    for (int t = 0; t < KNN; t++) sbd[t * TPB + tid] = bd[t];
    __syncthreads();

    // ---- Owner merges the two 30-lists: global 30th-smallest value.
    if (half == 0) {
        int ia = KNN - 1, ib = KNN - 1;   // smallest at row KNN-1
        float v = FMAXV;
        #pragma unroll
        for (int t = 0; t < KNN; t++) {
            float a = sbd[ia * TPB + tid];
            float b = sbd[ib * TPB + tid + PPB];
            if (a <= b) { v = a; ia--; } else { v = b; ib--; }
        }
        sthr[pid] = v;
    }
    __syncthreads();
    thr = sthr[pid];
    __syncthreads();   // all reads of sbd done before sidx overwrites it

    // ---- Pass 2 over this thread's half: collect strict (d<thr) and
    // ties (d==thr, ascending j, capped; overflow -> fallback).
    int cnt_s = 0, cnt_t = 0;
    #pragma unroll 4
    for (int pp = 0; pp < HALFP; pp++) {
        const int p = plo + pp;
        ulonglong2 P0 = sp2[2 * p];
        ulonglong2 P1 = sp2[2 * p + 1];
        u64 sump, mp, t1, dotp, dp;
        F2_ADD(sump, xxi2, P1.y);
        F2_MUL(mp, P0.x, xi2);
        F2_FMA(t1, P0.y, yi2, mp);
        F2_FMA(dotp, P1.x, zi2, t1);
        F2_FMA(dp, dotp, n2, sump);
        float d0, d1;
        unpack2(dp, d0, d1);
        if (fminf(d0, d1) <= thr) {
            const int j0 = 2 * p, j1 = 2 * p + 1;
            if (d0 <= thr) {
                if (d0 < thr) { sidx[cnt_s * TPB + tid] = j0; cnt_s++; }
                else { if (cnt_t < TIECAP) sties[cnt_t * TPB + tid] = j0; cnt_t++; }
            }
            if (d1 <= thr) {
                if (d1 < thr) { sidx[cnt_s * TPB + tid] = j1; cnt_s++; }
                else { if (cnt_t < TIECAP) sties[cnt_t * TPB + tid] = j1; cnt_t++; }
            }
        }
    }
    scnt[tid] = cnt_s;
    tcnt[tid] = cnt_t;
    __syncthreads();

    if (half == 1) return;   // owners do the epilogue

    // ---- Assemble neighbor set + streaming covariance (double) ----
    const int m_lo = scnt[tid], m_hi = scnt[tid + PPB];
    const int t_lo = tcnt[tid], t_hi = tcnt[tid + PPB];
    const int m = m_lo + m_hi;
    const int r = KNN - m;                  // >= 1 (the 30th itself is a tie)
    const int take_lo = (r < t_lo) ? r : t_lo;
    const int take_hi = r - take_lo;

    double s1x = 0, s1y = 0, s1z = 0;
    double sxx2 = 0, sxy = 0, sxz = 0, syy = 0, syz = 0, szz = 0;
    #define ACC(J) do { float fx, fy, fz; fetch_pt(spair, (J), fx, fy, fz);    \
        double px = (double)fx, py = (double)fy, pz = (double)fz;              \
        s1x += px;  s1y += py;  s1z += pz;                                     \
        sxx2 += px * px; sxy += px * py; sxz += px * pz;                       \
        syy  += py * py; syz += py * pz; szz += pz * pz; } while (0)

    for (int t = 0; t < m_lo; t++) ACC(sidx[t * TPB + tid]);
    for (int t = 0; t < m_hi; t++) ACC(sidx[t * TPB + tid + PPB]);

    if (take_lo <= TIECAP && take_hi <= TIECAP) {
        for (int t = 0; t < take_lo; t++) ACC(sties[t * TPB + tid]);
        for (int t = 0; t < take_hi; t++) ACC(sties[t * TPB + tid + PPB]);
    } else {
        // Fallback (pathological tie count): serial ascending-j tie re-scan.
        int need = r;
        for (int j = 0; j < NPTS && need > 0; j++) {
            float fx, fy, fz; fetch_pt(spair, j, fx, fy, fz);
            const float4 Bj = spair[(j >> 1) * 2 + 1];
            float fw = (j & 1) ? Bj.w : Bj.z;
            float dot = __fmaf_rn(zi, fz, __fmaf_rn(yi, fy, __fmul_rn(xi, fx)));
            float d   = __fsub_rn(__fadd_rn(xxi, fw), __fmul_rn(2.0f, dot));
            if (d == thr) { ACC(j); need--; }
        }
    }
    #undef ACC

    const double invK = 1.0 / (double)KNN;
    double cx = s1x * invK, cy = s1y * invK, cz = s1z * invK;
    double a00 = sxx2 - (double)KNN * cx * cx;
    double a01 = sxy  - (double)KNN * cx * cy;
    double a02 = sxz  - (double)KNN * cx * cz;
    double a11 = syy  - (double)KNN * cy * cy;
    double a12 = syz  - (double)KNN * cy * cz;
    double a22 = szz  - (double)KNN * cz * cz;

    // ---- Smallest eigenpair of symmetric 3x3 (closed form, double) ----
    double vx = 1.0, vy = 0.0, vz = 0.0;
    double q  = (a00 + a11 + a22) / 3.0;
    double b00 = a00 - q, b11 = a11 - q, b22 = a22 - q;
    double p2 = b00 * b00 + b11 * b11 + b22 * b22
              + 2.0 * (a01 * a01 + a02 * a02 + a12 * a12);
    if (p2 > 0.0) {
        double p  = sqrt(p2 / 6.0);
        double ip = 1.0 / p;
        double c00 = b00 * ip, c11 = b11 * ip, c22 = b22 * ip;
        double c01 = a01 * ip, c02 = a02 * ip, c12 = a12 * ip;
        double detB = c00 * (c11 * c22 - c12 * c12)
                    - c01 * (c01 * c22 - c12 * c02)
                    + c02 * (c01 * c12 - c11 * c02);
        double rr = 0.5 * detB;
        rr = fmin(1.0, fmax(-1.0, rr));
        double phi = acos(rr) / 3.0;
        double lam = q + 2.0 * p * cos(phi + 2.0943951023931953); // smallest

        double m00 = a00 - lam, m11 = a11 - lam, m22 = a22 - lam;
        double u0x = a01 * a12 - a02 * m11;
        double u0y = a02 * a01 - m00 * a12;
        double u0z = m00 * m11 - a01 * a01;   // r0 x r1
        double u1x = a01 * m22 - a02 * a12;
        double u1y = a02 * a02 - m00 * m22;
        double u1z = m00 * a12 - a01 * a02;   // r0 x r2
        double u2x = m11 * m22 - a12 * a12;
        double u2y = a12 * a02 - a01 * m22;
        double u2z = a01 * a12 - m11 * a02;   // r1 x r2
        double n0 = u0x * u0x + u0y * u0y + u0z * u0z;
        double n1 = u1x * u1x + u1y * u1y + u1z * u1z;
        double nn2 = u2x * u2x + u2y * u2y + u2z * u2z;
        double bx = u0x, by = u0y, bz = u0z, bn = n0;
        if (n1 > bn)  { bx = u1x; by = u1y; bz = u1z; bn = n1; }
        if (nn2 > bn) { bx = u2x; by = u2y; bz = u2z; bn = nn2; }
        if (bn > 0.0) {
            double inv = rsqrt(bn);
            vx = bx * inv; vy = by * inv; vz = bz * inv;
        }
    }

    // ---- Orientation: flip so that dot(-x, v) >= 0 ----
    double dot2 = -((double)xi * vx + (double)yi * vy + (double)zi * vz);
    if (dot2 < 0.0) { vx = -vx; vy = -vy; vz = -vz; }

    // ---- Output: (4, 6, 8192): rows 0-2 copy of x, rows 3-5 normals ----
    float* __restrict__ ob = out + (size_t)batch * 6 * NPTS;
    ob[0 * NPTS + i] = xi;
    ob[1 * NPTS + i] = yi;
    ob[2 * NPTS + i] = zi;
    ob[3 * NPTS + i] = (float)vx;
    ob[4 * NPTS + i] = (float)vy;
    ob[5 * NPTS + i] = (float)vz;
}

extern "C" void kernel_launch(void* const* d_in, const int* in_sizes, int n_in,
                              void* d_out, int out_size)
{
    (void)in_sizes; (void)n_in; (void)out_size;
    const float* x = (const float*)d_in[0];
    float* out = (float*)d_out;

    cudaFuncSetAttribute(knn_normals_kernel,
                         cudaFuncAttributeMaxDynamicSharedMemorySize, SMEM_BYTES);
    knn_normals_kernel<<<GRID, TPB, SMEM_BYTES>>>(x, out);
}

// round 16
// speedup vs baseline: 1.8864x; 1.8864x over previous
#include <cuda_runtime.h>
#include <math.h>

#define NPTS 8192
#define NPAIRS (NPTS / 2)        // 4096
#define NBATCH 4
#define KNN 30
#define TPB 1024
#define PPB 256                  // points per block
#define SUBS 4
#define SUBPAIRS (NPAIRS / SUBS) // 1024 pairs per sub-thread
#define CHUNKS (NPTS / PPB)      // 32
#define GRID (NBATCH * CHUNKS)   // 128
#define FMAXV 3.4028235e38f
#define TIECAP 8

typedef unsigned long long u64;

#define F2_FMA(o,a,b,c) asm("fma.rn.f32x2 %0,%1,%2,%3;" : "=l"(o) : "l"(a),"l"(b),"l"(c))
#define F2_MUL(o,a,b)   asm("mul.rn.f32x2 %0,%1,%2;"    : "=l"(o) : "l"(a),"l"(b))
#define F2_ADD(o,a,b)   asm("add.rn.f32x2 %0,%1,%2;"    : "=l"(o) : "l"(a),"l"(b))

__device__ __forceinline__ u64 pack2(float lo, float hi) {
    u64 r; asm("mov.b64 %0,{%1,%2};" : "=l"(r) : "f"(lo), "f"(hi)); return r;
}
__device__ __forceinline__ void unpack2(u64 v, float& lo, float& hi) {
    asm("mov.b64 {%0,%1},%2;" : "=f"(lo), "=f"(hi) : "l"(v));
}

// smem layout (bytes)
#define OFF_SP    0                         // float4 spair[NPTS]      131072
#define OFF_G     131072                    // float gf[1024]          +4096
#define OFF_MRG   135168                    // float smrg[30][512]     +61440
#define OFF_THR   196608                    // float thr30[256]        +1024
#define OFF_SCNT  197632                    // int scnt[256]           +1024
#define OFF_TCNT  198656                    // int tcnt[256]           +1024
#define SMEM_BYTES 199680
// pass-2 reuse of the merge buffer:
#define OFF_STR   OFF_MRG                   // int sstr[256][32]        32768
#define OFF_TIE   (OFF_MRG + 32768)         // int stie[256][TIECAP]     8192

__device__ __forceinline__ void fetch_pt(const float4* sp, int j,
                                         float& px, float& py, float& pz) {
    const float4 A = sp[(j >> 1) * 2];
    const float4 B = sp[(j >> 1) * 2 + 1];
    const bool hi = j & 1;
    px = hi ? A.y : A.x;
    py = hi ? A.w : A.z;
    pz = hi ? B.y : B.x;
}

// Depth-2 evict-max insert into descending sorted bd[0..29] (bd[0]=max).
__device__ __forceinline__ void insert30(float (&bd)[KNN], float d) {
    #pragma unroll
    for (int t = 0; t < KNN; t++) {
        float below = (t < KNN - 1) ? bd[t + 1] : -FMAXV;
        bd[t] = fminf(bd[t], fmaxf(below, d));
    }
}

__global__ __launch_bounds__(TPB, 1) void knn_normals_kernel(
    const float* __restrict__ x, float* __restrict__ out)
{
    extern __shared__ char smem_raw[];
    float4* spair = (float4*)(smem_raw + OFF_SP);
    float*  gf    = (float*)(smem_raw + OFF_G);
    float*  smrg  = (float*)(smem_raw + OFF_MRG);
    float*  thr30 = (float*)(smem_raw + OFF_THR);
    int*    scnt  = (int*)(smem_raw + OFF_SCNT);
    int*    tcnt  = (int*)(smem_raw + OFF_TCNT);
    int*    sstr  = (int*)(smem_raw + OFF_STR);
    int*    stie  = (int*)(smem_raw + OFF_TIE);

    const int tid = threadIdx.x;
    const int pid = tid & (PPB - 1);
    const int sub = tid >> 8;                 // 0..3
    const int plo = sub * SUBPAIRS;

    const int batch = blockIdx.x / CHUNKS;
    const int chunk = blockIdx.x % CHUNKS;
    const float* __restrict__ xb = x + (size_t)batch * 3 * NPTS;

    // Pair-packed smem: spair[2p]=(x0,x1,y0,y1), spair[2p+1]=(z0,z1,xx0,xx1).
    // xx rounded exactly as the reference (squares, then left-to-right sum).
    for (int p = tid; p < NPAIRS; p += TPB) {
        int j0 = 2 * p, j1 = 2 * p + 1;
        float x0 = xb[j0],            x1 = xb[j1];
        float y0 = xb[NPTS + j0],     y1 = xb[NPTS + j1];
        float z0 = xb[2 * NPTS + j0], z1 = xb[2 * NPTS + j1];
        float w0 = __fadd_rn(__fadd_rn(__fmul_rn(x0, x0), __fmul_rn(y0, y0)),
                             __fmul_rn(z0, z0));
        float w1 = __fadd_rn(__fadd_rn(__fmul_rn(x1, x1), __fmul_rn(y1, y1)),
                             __fmul_rn(z1, z1));
        spair[2 * p]     = make_float4(x0, x1, y0, y1);
        spair[2 * p + 1] = make_float4(z0, z1, w0, w1);
    }
    gf[tid] = FMAXV;
    if (tid < PPB) { scnt[tid] = 0; tcnt[tid] = 0; }
    __syncthreads();

    const int i = chunk * PPB + pid;
    float xi, yi, zi;
    fetch_pt(spair, i, xi, yi, zi);
    const float4 Bi = spair[(i >> 1) * 2 + 1];
    const float xxi = (i & 1) ? Bi.w : Bi.z;

    const u64 xi2 = pack2(xi, xi), yi2 = pack2(yi, yi), zi2 = pack2(zi, zi);
    const u64 xxi2 = pack2(xxi, xxi), c_n2 = pack2(-2.0f, -2.0f);
    const ulonglong2* __restrict__ sp2 = (const ulonglong2*)spair;

    // ---- Pass 1 over this sub's 1024 pairs. Admission gated by
    // thrEff = min(own bd[0], gate), gate = max over subs of published bd[22].
    // gate >= d30 for any timing (else >=30 distinct elements < d30).
    float bd[KNN];
    #pragma unroll
    for (int t = 0; t < KNN; t++) bd[t] = FMAXV;
    float* gslot = gf + sub * PPB + pid;      // single-writer slot

    for (int blk = 0; blk < SUBPAIRS / 8; blk++) {
        float g01 = fmaxf(gf[pid],           gf[PPB + pid]);
        float g23 = fmaxf(gf[2 * PPB + pid], gf[3 * PPB + pid]);
        const float gate = fmaxf(g01, g23);
        float thrEff = fminf(bd[0], gate);
        #pragma unroll
        for (int u = 0; u < 8; u++) {
            const int p = plo + blk * 8 + u;
            ulonglong2 P0 = sp2[2 * p];       // (x0,x1 | y0,y1)
            ulonglong2 P1 = sp2[2 * p + 1];   // (z0,z1 | xx0,xx1)
            u64 sump, mp, t1, dotp, dp;
            F2_ADD(sump, xxi2, P1.y);
            F2_MUL(mp, P0.x, xi2);
            F2_FMA(t1, P0.y, yi2, mp);
            F2_FMA(dotp, P1.x, zi2, t1);
            F2_FMA(dp, dotp, c_n2, sump);     // (xxi+xxj) - 2*dot, 1 rounding
            float d0, d1;
            unpack2(dp, d0, d1);
            if (fminf(d0, d1) < thrEff) {
                if (d0 < thrEff) { insert30(bd, d0); thrEff = fminf(bd[0], gate); }
                if (d1 < thrEff) { insert30(bd, d1); thrEff = fminf(bd[0], gate); }
            }
        }
        *gslot = bd[22];                      // publish running 8th-smallest
    }

    // ---- Phased exact merge of the 4 sorted lists -> thr = global d30.
    // smrg columns: [pid] = accumulated merged list, [256+pid] = incoming.
    if (sub == 0) {
        #pragma unroll
        for (int t = 0; t < KNN; t++) smrg[t * 512 + pid] = bd[t];
    }
    if (sub == 1) {
        #pragma unroll
        for (int t = 0; t < KNN; t++) smrg[t * 512 + 256 + pid] = bd[t];
    }
    __syncthreads();
    if (sub == 0) {                           // merge(acc, sub1) -> acc
        float m[KNN]; int ia = KNN - 1, ib = KNN - 1;
        #pragma unroll
        for (int k = KNN - 1; k >= 0; k--) {
            float a = smrg[ia * 512 + pid];
            float b = smrg[ib * 512 + 256 + pid];
            if (a <= b) { m[k] = a; ia--; } else { m[k] = b; ib--; }
        }
        #pragma unroll
        for (int t = 0; t < KNN; t++) smrg[t * 512 + pid] = m[t];
    }
    __syncthreads();
    if (sub == 2) {
        #pragma unroll
        for (int t = 0; t < KNN; t++) smrg[t * 512 + 256 + pid] = bd[t];
    }
    __syncthreads();
    if (sub == 0) {                           // merge(acc, sub2) -> acc
        float m[KNN]; int ia = KNN - 1, ib = KNN - 1;
        #pragma unroll
        for (int k = KNN - 1; k >= 0; k--) {
            float a = smrg[ia * 512 + pid];
            float b = smrg[ib * 512 + 256 + pid];
            if (a <= b) { m[k] = a; ia--; } else { m[k] = b; ib--; }
        }
        #pragma unroll
        for (int t = 0; t < KNN; t++) smrg[t * 512 + pid] = m[t];
    }
    __syncthreads();
    if (sub == 3) {
        #pragma unroll
        for (int t = 0; t < KNN; t++) smrg[t * 512 + 256 + pid] = bd[t];
    }
    __syncthreads();
    if (sub == 0) {                           // final: need only the 30th value
        int ia = KNN - 1, ib = KNN - 1; float v = FMAXV;
        #pragma unroll
        for (int k = 0; k < KNN; k++) {
            float a = smrg[ia * 512 + pid];
            float b = smrg[ib * 512 + 256 + pid];
            if (a <= b) { v = a; ia--; } else { v = b; ib--; }
        }
        thr30[pid] = v;
    }
    __syncthreads();
    const float thr = thr30[pid];
    __syncthreads();                          // smrg free for reuse below

    // ---- Pass 2: collect strict (d<thr, <=29 total) and ties (d==thr) into
    // per-point columns via smem atomics; order fixed later by sorting.
    for (int pp = 0; pp < SUBPAIRS; pp++) {
        const int p = plo + pp;
        ulonglong2 P0 = sp2[2 * p];
        ulonglong2 P1 = sp2[2 * p + 1];
        u64 sump, mp, t1, dotp, dp;
        F2_ADD(sump, xxi2, P1.y);
        F2_MUL(mp, P0.x, xi2);
        F2_FMA(t1, P0.y, yi2, mp);
        F2_FMA(dotp, P1.x, zi2, t1);
        F2_FMA(dp, dotp, c_n2, sump);
        float d0, d1;
        unpack2(dp, d0, d1);
        if (fminf(d0, d1) <= thr) {
            const int j0 = 2 * p, j1 = 2 * p + 1;
            if (d0 <= thr) {
                if (d0 < thr) sstr[pid * 32 + atomicAdd(&scnt[pid], 1)] = j0;
                else { int s = atomicAdd(&tcnt[pid], 1);
                       if (s < TIECAP) stie[pid * TIECAP + s] = j0; }
            }
            if (d1 <= thr) {
                if (d1 < thr) sstr[pid * 32 + atomicAdd(&scnt[pid], 1)] = j1;
                else { int s = atomicAdd(&tcnt[pid], 1);
                       if (s < TIECAP) stie[pid * TIECAP + s] = j1; }
            }
        }
    }
    __syncthreads();

    if (sub != 0) return;                     // owners do the epilogue

    const int m = scnt[pid];                  // <= 29 by definition of d30
    const int tc = tcnt[pid];
    const int r = KNN - m;                    // >= 1

    // Sort strict column ascending (deterministic accumulation order).
    for (int a = 1; a < m; a++) {
        int v = sstr[pid * 32 + a]; int b = a - 1;
        while (b >= 0 && sstr[pid * 32 + b] > v) {
            sstr[pid * 32 + b + 1] = sstr[pid * 32 + b]; b--;
        }
        sstr[pid * 32 + b + 1] = v;
    }

    double s1x = 0, s1y = 0, s1z = 0;
    double sxx2 = 0, sxy = 0, sxz = 0, syy = 0, syz = 0, szz = 0;
    #define ACC(J) do { float fx, fy, fz; fetch_pt(spair, (J), fx, fy, fz);    \
        double px = (double)fx, py = (double)fy, pz = (double)fz;              \
        s1x += px;  s1y += py;  s1z += pz;                                     \
        sxx2 += px * px; sxy += px * py; sxz += px * pz;                       \
        syy  += py * py; syz += py * pz; szz += pz * pz; } while (0)

    for (int t = 0; t < m; t++) ACC(sstr[pid * 32 + t]);

    if (tc <= TIECAP) {
        // complete tie set stored: sort ascending, take lowest-j r of them.
        for (int a = 1; a < tc; a++) {
            int v = stie[pid * TIECAP + a]; int b = a - 1;
            while (b >= 0 && stie[pid * TIECAP + b] > v) {
                stie[pid * TIECAP + b + 1] = stie[pid * TIECAP + b]; b--;
            }
            stie[pid * TIECAP + b + 1] = v;
        }
        for (int t = 0; t < r; t++) ACC(stie[pid * TIECAP + t]);
    } else {
        // pathological tie count: deterministic serial ascending-j re-scan.
        int need = r;
        for (int j = 0; j < NPTS && need > 0; j++) {
            float fx, fy, fz; fetch_pt(spair, j, fx, fy, fz);
            const float4 Bj = spair[(j >> 1) * 2 + 1];
            float fw = (j & 1) ? Bj.w : Bj.z;
            float dot = __fmaf_rn(zi, fz, __fmaf_rn(yi, fy, __fmul_rn(xi, fx)));
            float d   = __fsub_rn(__fadd_rn(xxi, fw), __fmul_rn(2.0f, dot));
            if (d == thr) { ACC(j); need--; }
        }
    }
    #undef ACC

    const double invK = 1.0 / (double)KNN;
    double cx = s1x * invK, cy = s1y * invK, cz = s1z * invK;
    double a00 = sxx2 - (double)KNN * cx * cx;
    double a01 = sxy  - (double)KNN * cx * cy;
    double a02 = sxz  - (double)KNN * cx * cz;
    double a11 = syy  - (double)KNN * cy * cy;
    double a12 = syz  - (double)KNN * cy * cz;
    double a22 = szz  - (double)KNN * cz * cz;

    // ---- Smallest eigenpair of symmetric 3x3 (closed form, double) ----
    double vx = 1.0, vy = 0.0, vz = 0.0;
    double q  = (a00 + a11 + a22) / 3.0;
    double b00 = a00 - q, b11 = a11 - q, b22 = a22 - q;
    double p2 = b00 * b00 + b11 * b11 + b22 * b22
              + 2.0 * (a01 * a01 + a02 * a02 + a12 * a12);
    if (p2 > 0.0) {
        double p  = sqrt(p2 / 6.0);
        double ip = 1.0 / p;
        double c00 = b00 * ip, c11 = b11 * ip, c22 = b22 * ip;
        double c01 = a01 * ip, c02 = a02 * ip, c12 = a12 * ip;
        double detB = c00 * (c11 * c22 - c12 * c12)
                    - c01 * (c01 * c22 - c12 * c02)
                    + c02 * (c01 * c12 - c11 * c02);
        double rr = 0.5 * detB;
        rr = fmin(1.0, fmax(-1.0, rr));
        double phi = acos(rr) / 3.0;
        double lam = q + 2.0 * p * cos(phi + 2.0943951023931953); // smallest

        double m00 = a00 - lam, m11 = a11 - lam, m22 = a22 - lam;
        double u0x = a01 * a12 - a02 * m11;
        double u0y = a02 * a01 - m00 * a12;
        double u0z = m00 * m11 - a01 * a01;
        double u1x = a01 * m22 - a02 * a12;
        double u1y = a02 * a02 - m00 * m22;
        double u1z = m00 * a12 - a01 * a02;
        double u2x = m11 * m22 - a12 * a12;
        double u2y = a12 * a02 - a01 * m22;
        double u2z = a01 * a12 - m11 * a02;
        double n0 = u0x * u0x + u0y * u0y + u0z * u0z;
        double n1 = u1x * u1x + u1y * u1y + u1z * u1z;
        double nn2 = u2x * u2x + u2y * u2y + u2z * u2z;
        double bx = u0x, by = u0y, bz = u0z, bn = n0;
        if (n1 > bn)  { bx = u1x; by = u1y; bz = u1z; bn = n1; }
        if (nn2 > bn) { bx = u2x; by = u2y; bz = u2z; bn = nn2; }
        if (bn > 0.0) {
            double inv = rsqrt(bn);
            vx = bx * inv; vy = by * inv; vz = bz * inv;
        }
    }

    double dot2 = -((double)xi * vx + (double)yi * vy + (double)zi * vz);
    if (dot2 < 0.0) { vx = -vx; vy = -vy; vz = -vz; }

    float* __restrict__ ob = out + (size_t)batch * 6 * NPTS;
    ob[0 * NPTS + i] = xi;
    ob[1 * NPTS + i] = yi;
    ob[2 * NPTS + i] = zi;
    ob[3 * NPTS + i] = (float)vx;
    ob[4 * NPTS + i] = (float)vy;
    ob[5 * NPTS + i] = (float)vz;
}

extern "C" void kernel_launch(void* const* d_in, const int* in_sizes, int n_in,
                              void* d_out, int out_size)
{
    (void)in_sizes; (void)n_in; (void)out_size;
    const float* x = (const float*)d_in[0];
    float* out = (float*)d_out;

    cudaFuncSetAttribute(knn_normals_kernel,
                         cudaFuncAttributeMaxDynamicSharedMemorySize, SMEM_BYTES);
    knn_normals_kernel<<<GRID, TPB, SMEM_BYTES>>>(x, out);
}